// round 14
// baseline (speedup 1.0000x reference)
#include <cuda_runtime.h>

// ---------------- problem constants (fixed by setup_inputs) ----------------
#define G        64      // gt boxes per batch
#define A        5       // anchors per location
#define S        25      // score map size
#define NANCH    3125    // S*S*A
#define NPAD     3128    // g_cls row stride (4-byte aligned)
#define BMAX     128
#define POS_NUM  16
#define TOTAL_NUM 64
#define THR_HIGH 0.6f
#define THR_LOW  0.3f
#define TPB      1024
#define HALF     2048    // anchors per x-block (grid.x = 2)

// ---------------- scratch (device globals) -----------------------------------
__device__ signed char   g_cls[BMAX * NPAD];    // pre-truncation cls (padded)
__device__ unsigned char g_arg[BMAX * NANCH];   // per-anchor argmax gt

// ---------------- smem layout for k_iou (~70 KB -> 2 blocks/SM) --------------
struct SM {
    float    xc[G * 128];       // clamped x-overlap [g][px*5+a]
    float    yc[G * 128];       // clamped y-overlap [g][py*5+a]
    float2   sgp[G * 8];        // {area_a+area_g, gtmax-or-NaN-sentinel} [g][a]
    float4   gtv[G];
    float    gar[G];            // gt areas
    unsigned gtm[G];            // per-g global max iou bits (atomicMax target)
};

// Correctly-rounded fp32 divide, fast path only (no FCHK / slow-path branch).
// RCP + 2 Newton + Markstein 2-FMA finish: bitwise == div.rn.f32 for normal
// operands with normal quotient (this kernel's entire domain). Used for BOTH
// the gtmax table and the per-anchor IoUs -> keep-equality self-consistent.
__device__ __forceinline__ float div_rn_fast(float n, float d) {
    float r;
    asm("rcp.approx.f32 %0, %1;" : "=f"(r) : "f"(d));
    r = __fmaf_rn(__fmaf_rn(-d, r, 1.0f), r, r);
    r = __fmaf_rn(__fmaf_rn(-d, r, 1.0f), r, r);
    float q = __fmul_rn(n, r);
    return __fmaf_rn(__fmaf_rn(-d, q, n), r, q);
}

// ---------------- K1: mask-loop IoU: max/arg/keep/cls/maxov ------------------
// grid (2, B), block 1024, 2 blocks/SM. Phase 1 builds a warp-uniform 64-bit
// activity mask (branch-free); phase 2 visits only active g's.
__global__ void __launch_bounds__(TPB, 2)
k_iou(const float4* __restrict__ anchors,
      const float4* __restrict__ gt,
      float* __restrict__ out, int Bn) {
    extern __shared__ char smraw[];
    SM* s = (SM*)smraw;
    const int bx = blockIdx.x, bA = blockIdx.y, t = threadIdx.x;

    if (t < G) {
        float4 q = gt[bA * G + t];
        s->gtv[t] = q;
        float gw = __fadd_rn(__fsub_rn(q.z, q.x), 1.0f);
        float gh = __fadd_rn(__fsub_rn(q.w, q.y), 1.0f);
        s->gar[t] = __fmul_rn(gw, gh);
        s->gtm[t] = 0u;
    }
    __syncthreads();

    // ---- clamped 1D overlap tables (exact _rn ops, same as reference) -------
    // Separable grid: x-coords of anchor (py,px,a) equal anchors[px*5+a]'s;
    // y-coords equal anchors[py*125+a]'s.
    for (int i = t; i < G * 125; i += TPB) {
        int g = i / 125, j = i - g * 125;
        float4 q = s->gtv[g];
        float4 ax = anchors[j];
        float ix = __fadd_rn(__fsub_rn(fminf(ax.z, q.z), fmaxf(ax.x, q.x)), 1.0f);
        s->xc[g * 128 + j] = fmaxf(ix, 0.0f);
        int py = j / 5, a = j - py * 5;
        float4 ay = anchors[py * 125 + a];
        float iy = __fadd_rn(__fsub_rn(fminf(ay.w, q.w), fmaxf(ay.y, q.y)), 1.0f);
        s->yc[g * 128 + j] = fmaxf(iy, 0.0f);
    }
    __syncthreads();

    // ---- gtmax from tables (bitwise exact): fmul_rn monotone on nonneg args,
    // the divide monotone in I -> per-(g,shape) max-I anchor attains the max.
    if (t < G * A) {
        int g = t / A, a = t - (t / A) * A;
        float xm = 0.0f, ym = 0.0f;
        for (int p = 0; p < S; p++) {
            xm = fmaxf(xm, s->xc[g * 128 + p * 5 + a]);
            ym = fmaxf(ym, s->yc[g * 128 + p * 5 + a]);
        }
        float4 a4 = anchors[a];
        float aw = __fadd_rn(__fsub_rn(a4.z, a4.x), 1.0f);
        float ah = __fadd_rn(__fsub_rn(a4.w, a4.y), 1.0f);
        float I  = __fmul_rn(xm, ym);
        float v  = div_rn_fast(I, __fsub_rn(__fadd_rn(__fmul_rn(aw, ah),
                                                      s->gar[g]), I));
        if (I > 0.0f) atomicMax(&s->gtm[g], __float_as_uint(v));
    }
    __syncthreads();
    // ---- packed {sag, gtmS} table (one LDS.64 in the hot loop) --------------
    if (t < G * 8) {
        int g = t >> 3, a = t & 7;
        float4 a4 = anchors[a < A ? a : 0];
        float aw = __fadd_rn(__fsub_rn(a4.z, a4.x), 1.0f);
        float ah = __fadd_rn(__fsub_rn(a4.w, a4.y), 1.0f);
        unsigned gm = s->gtm[g];
        float2 p;
        p.x = __fadd_rn(__fmul_rn(aw, ah), s->gar[g]);
        p.y = __uint_as_float(gm ? gm : 0xFFFFFFFFu);   // NaN bits: never ties
        s->sgp[t] = p;
    }
    __syncthreads();

    // ---- main loop: 2 chunks of 1024 anchors per x-block --------------------
    for (int c = 0; c < 2; c++) {
        const int  n   = bx * HALF + c * TPB + t;
        const bool val = (n < NANCH);
        if (!__ballot_sync(0xffffffffu, val)) continue;   // whole-warp invalid
        const int nn   = val ? n : NANCH - 1;
        const int xoff = nn % 125;
        const int yoff = (nn / 125) * 5 + (nn % 5);
        const int aoff = nn % 5;

        const float*  xp = s->xc + xoff;      // + g*128
        const float*  yp = s->yc + yoff;      // + g*128
        const float2* sp = s->sgp + aoff;     // + g*8

        // Phase 1: warp-uniform activity masks (branch-free, unrolled)
        unsigned act0 = 0u, act1 = 0u;
#pragma unroll
        for (int g = 0; g < 32; g++) {
            float inter = __fmul_rn(xp[g * 128], yp[g * 128]);
            if (__any_sync(0xffffffffu, inter > 0.0f)) act0 |= 1u << g;
        }
#pragma unroll
        for (int g = 32; g < G; g++) {
            float inter = __fmul_rn(xp[g * 128], yp[g * 128]);
            if (__any_sync(0xffffffffu, inter > 0.0f)) act1 |= 1u << (g - 32);
        }

        // Phase 2: visit active g's only. Descending g + ">=" update =
        // first-index argmax semantics (ties resolve toward lower g).
        float max0 = -1.0f, max1 = -1.0f;
        int   arg0 = 0,     arg1 = 0;
        bool  keep = false;

        while (act0) {
            int g = 31 - __clz(act0);
            act0 ^= 1u << g;
            float2 sg = sp[g * 8];
            float inter = __fmul_rn(xp[g * 128], yp[g * 128]);
            float v = div_rn_fast(inter, __fsub_rn(sg.x, inter));
            if (v >= max0) { max0 = v; arg0 = g; }
            keep |= (__float_as_uint(v) == __float_as_uint(sg.y));
        }
        while (act1) {
            int g = 31 - __clz(act1);
            act1 ^= 1u << g;
            float2 sg = sp[(g + 32) * 8];
            float inter = __fmul_rn(xp[(g + 32) * 128], yp[(g + 32) * 128]);
            float v = div_rn_fast(inter, __fsub_rn(sg.x, inter));
            if (v >= max1) { max1 = v; arg1 = g + 32; }
            keep |= (__float_as_uint(v) == __float_as_uint(sg.y));
        }

        float maxv = max0; int arg = arg0;                // cross-half tie ->
        if (max1 > max0) { maxv = max1; arg = arg1; }     // low half (first idx)
        if (maxv <= 0.0f) { maxv = 0.0f; arg = 0; }       // all-zero row

        if (val) {
            const long idx = (long)bA * NANCH + n;
            int cls = -1;
            if (maxv >= THR_HIGH) cls = 1;
            if (maxv <= THR_LOW)  cls = 0;
            if (keep)             cls = 1;
            g_cls[(long)bA * NPAD + n] = (signed char)cls;
            g_arg[idx] = (unsigned char)arg;
            out[(long)Bn * NANCH * 6 + idx] = maxv;
        }
    }
    if (bx == 1 && t < NPAD - NANCH)                      // pad tail -> -1
        g_cls[(long)bA * NPAD + NANCH + t] = -1;
}

// ---------------- K1b: bt deltas from stored argmax --------------------------
// grid (4, B), block 1024, one anchor/thread.
__global__ void k_bt(const float4* __restrict__ anchors,
                     const float4* __restrict__ gt,
                     float* __restrict__ out, int Bn) {
    const int bA = blockIdx.y;
    const int n  = blockIdx.x * TPB + threadIdx.x;
    if (n >= NANCH) return;
    float4 a4 = anchors[n];
    float4 q  = gt[bA * G + g_arg[(long)bA * NANCH + n]];

    float aw = a4.z - a4.x + 1.0f, ah = a4.w - a4.y + 1.0f;
    float acx = a4.x + 0.5f * aw,  acy = a4.y + 0.5f * ah;
    float gw = q.z - q.x + 1.0f,   gh = q.w - q.y + 1.0f;
    float gcx = q.x + 0.5f * gw,   gcy = q.y + 0.5f * gh;
    float dx = __fdividef(gcx - acx, aw);
    float dy = __fdividef(gcy - acy, ah);
    float dw = __logf(__fdividef(gw, aw));
    float dh = __logf(__fdividef(gh, ah));

    const int aa = n % A, yx = n / A;
    long o = (long)Bn * NANCH + ((long)(bA * 4) * A + aa) * (S * S) + yx;
    out[o]             = dx;
    out[o + NANCH]     = dy;          // +1 delta-channel = +A*S*S
    out[o + 2 * NANCH] = dw;
    out[o + 3 * NANCH] = dh;
}

// ---------------- K2: per-batch cumsum truncation, coalesced cls/bw ----------
__global__ void k_scan(float* __restrict__ out, int Bn) {
    __shared__ int wsum[32];
    __shared__ int s_pos;
    __shared__ signed char s_cls[NANCH + 3];
    const int bA = blockIdx.x, t = threadIdx.x;
    const int lane = t & 31, w = t >> 5;
    const int bL = Bn - 1;

    if (t == 0) s_pos = 0;
    __syncthreads();

    // pre-truncation pos count of LAST batch (post-trunc = min(raw, POS_NUM))
    const int NI = NPAD / 4;                             // 782 ints
    int lp = 0;
    if (t < NI) {
        int x = ((const int*)g_cls)[(long)bL * NI + t];
        lp = __popc(__vcmpeq4((unsigned)x, 0x01010101u)) >> 3;
    }
#pragma unroll
    for (int off = 16; off; off >>= 1) lp += __shfl_down_sync(0xffffffffu, lp, off);
    if (lane == 0 && lp) atomicAdd(&s_pos, lp);

    // own chunk of 4 (one aligned 32-bit load)
    int cloc[4];
    int pc = 0, nc = 0;
    if (t < NI) {
        int x = ((const int*)g_cls)[(long)bA * NI + t];
#pragma unroll
        for (int k = 0; k < 4; k++) {
            int c = (signed char)(x >> (8 * k));
            cloc[k] = c;
            pc += (c == 1);
            nc += (c == 0);
        }
    } else {
        cloc[0] = cloc[1] = cloc[2] = cloc[3] = -1;
    }

    // block-wide exclusive scan of packed (pos,neg) counts
    int v = (pc << 16) | nc;
    int inc = v;
#pragma unroll
    for (int off = 1; off < 32; off <<= 1) {
        int u = __shfl_up_sync(0xffffffffu, inc, off);
        if (lane >= off) inc += u;
    }
    if (lane == 31) wsum[w] = inc;
    __syncthreads();
    if (w == 0) {
        int x = wsum[lane];
        int xi = x;
#pragma unroll
        for (int off = 1; off < 32; off <<= 1) {
            int u = __shfl_up_sync(0xffffffffu, xi, off);
            if (lane >= off) xi += u;
        }
        wsum[lane] = xi - x;
    }
    __syncthreads();
    int exc = (inc - v) + wsum[w];
    int prun = exc >> 16;
    int nrun = exc & 0xffff;

    const int start = t * 4;
#pragma unroll
    for (int k = 0; k < 4; k++) {
        int n = start + k;
        if (n >= NANCH) break;
        int c = cloc[k];
        if (c == 1)      { prun++; if (prun > POS_NUM)   c = -1; }
        else if (c == 0) { nrun++; if (nrun > TOTAL_NUM) c = -1; }
        s_cls[n] = (signed char)c;
    }
    __syncthreads();

    const int pn = min(s_pos, POS_NUM);
    const float invp = 1.0f / (float)pn;                 // pn==0 -> inf (ref)
    const long clsB = (long)bA * NANCH;
    const long bwB  = (long)Bn * NANCH * 5 + clsB;

    for (int o = t; o < NANCH; o += 1024) {              // o = a*625+yx, coalesced
        int aa = o / (S * S), yx = o - aa * (S * S);
        int c = s_cls[yx * A + aa];                      // stride-5 LDS: no conflicts
        out[clsB + o] = (float)c;
        out[bwB + o]  = (c == 1) ? invp : 0.0f;
    }
}

// ---------------- launch ------------------------------------------------------
extern "C" void kernel_launch(void* const* d_in, const int* in_sizes, int n_in,
                              void* d_out, int out_size) {
    (void)n_in; (void)out_size;
    const float4* gt      = (const float4*)d_in[0];   // (B, G, 4)
    const float4* anchors = (const float4*)d_in[1];   // (N, 4)
    const int Bn = in_sizes[0] / (G * 4);             // 128
    float* out = (float*)d_out;

    static int smem_set = 0;
    if (!smem_set) {
        cudaFuncSetAttribute(k_iou, cudaFuncAttributeMaxDynamicSharedMemorySize,
                             (int)sizeof(SM));
        smem_set = 1;
    }
    k_iou <<<dim3(2, Bn), TPB, sizeof(SM)>>>(anchors, gt, out, Bn);
    k_bt  <<<dim3(4, Bn), TPB>>>(anchors, gt, out, Bn);
    k_scan<<<Bn, 1024>>>(out, Bn);
}

// round 15
// speedup vs baseline: 1.6033x; 1.6033x over previous
#include <cuda_runtime.h>

// ---------------- problem constants (fixed by setup_inputs) ----------------
#define G        64      // gt boxes per batch
#define A        5       // anchors per location
#define S        25      // score map size
#define NLOC     625     // S*S grid locations
#define NANCH    3125    // NLOC*A
#define NPAD     3128    // g_cls row stride (4-byte aligned)
#define BMAX     128
#define POS_NUM  16
#define TOTAL_NUM 64
#define THR_HIGH 0.6f
#define THR_LOW  0.3f
#define TPB      1024

// ---------------- scratch (device global) ------------------------------------
__device__ signed char g_cls[BMAX * NPAD];   // pre-truncation cls (padded rows)

// ---------------- smem layout for k_iou (~69 KB, 1 block/SM) -----------------
struct SM {
    float    xc[G * 128];       // clamped x-overlap [g][px*5+a]
    float    yc[G * 128];       // clamped y-overlap [g][py*5+a]
    float    sag[G * 8];        // area_a(shape) + area_g   [g][a]
    unsigned gtmS[G];           // gtmax bits or 0xFFFFFFFF sentinel
    float4   gtv[G];
    float    gar[G];            // gt areas
    unsigned gtm[G];            // per-g global max iou bits (atomicMax target)
};

// Correctly-rounded fp32 divide, fast path (canonical libdevice div.rn fast
// sequence: RCP + one Newton + Markstein finish; 6 instructions, no FCHK).
// Valid for normal operands/quotients — this kernel's entire domain. Used for
// BOTH the gtmax table and per-anchor IoUs -> keep-equality self-consistent.
__device__ __forceinline__ float div6(float n, float d) {
    float r;
    asm("rcp.approx.f32 %0, %1;" : "=f"(r) : "f"(d));
    r = __fmaf_rn(__fmaf_rn(-d, r, 1.0f), r, r);
    float q = __fmul_rn(n, r);
    return __fmaf_rn(__fmaf_rn(-d, q, n), r, q);
}

// ---------------- K1: one thread = one location (5 shapes) -------------------
// grid = B blocks of 1024 (625 active in main loop). Fuses IoU, max/arg, keep,
// cls, maxov AND bt deltas (arg already in registers).
__global__ void __launch_bounds__(TPB, 1)
k_iou(const float4* __restrict__ anchors,
      const float4* __restrict__ gt,
      float* __restrict__ out, int Bn) {
    extern __shared__ char smraw[];
    SM* s = (SM*)smraw;
    const int bA = blockIdx.x, t = threadIdx.x;

    if (t < G) {
        float4 q = gt[bA * G + t];
        s->gtv[t] = q;
        float gw = __fadd_rn(__fsub_rn(q.z, q.x), 1.0f);
        float gh = __fadd_rn(__fsub_rn(q.w, q.y), 1.0f);
        s->gar[t] = __fmul_rn(gw, gh);
        s->gtm[t] = 0u;
    }
    __syncthreads();

    // ---- clamped 1D overlap tables (exact _rn ops, same as reference) -------
    // Separable grid: x-coords of anchor (py,px,a) equal anchors[px*5+a]'s;
    // y-coords equal anchors[py*125+a]'s.
    for (int i = t; i < G * 125; i += TPB) {
        int g = i / 125, j = i - g * 125;
        float4 q = s->gtv[g];
        float4 ax = anchors[j];
        float ix = __fadd_rn(__fsub_rn(fminf(ax.z, q.z), fmaxf(ax.x, q.x)), 1.0f);
        s->xc[g * 128 + j] = fmaxf(ix, 0.0f);
        int py = j / 5, a = j - py * 5;
        float4 ay = anchors[py * 125 + a];
        float iy = __fadd_rn(__fsub_rn(fminf(ay.w, q.w), fmaxf(ay.y, q.y)), 1.0f);
        s->yc[g * 128 + j] = fmaxf(iy, 0.0f);
    }
    __syncthreads();

    // ---- gtmax from tables (bitwise exact: fmul_rn monotone on nonneg args,
    // div monotone in I -> per-(g,shape) max-I anchor attains the max), plus
    // the sag table (area_a + area_g).
    if (t < G * A) {
        int g = t / A, a = t - (t / A) * A;
        float xm = 0.0f, ym = 0.0f;
        for (int p = 0; p < S; p++) {
            xm = fmaxf(xm, s->xc[g * 128 + p * 5 + a]);
            ym = fmaxf(ym, s->yc[g * 128 + p * 5 + a]);
        }
        float4 a4 = anchors[a];
        float aw = __fadd_rn(__fsub_rn(a4.z, a4.x), 1.0f);
        float ah = __fadd_rn(__fsub_rn(a4.w, a4.y), 1.0f);
        float I  = __fmul_rn(xm, ym);
        float v  = div6(I, __fsub_rn(__fadd_rn(__fmul_rn(aw, ah),
                                               s->gar[g]), I));
        if (I > 0.0f) atomicMax(&s->gtm[g], __float_as_uint(v));
    }
    if (t < G * 8) {
        int g = t >> 3, a = t & 7;
        float4 a4 = anchors[a < A ? a : 0];
        float aw = __fadd_rn(__fsub_rn(a4.z, a4.x), 1.0f);
        float ah = __fadd_rn(__fsub_rn(a4.w, a4.y), 1.0f);
        s->sag[t] = __fadd_rn(__fmul_rn(aw, ah), s->gar[g]);
    }
    __syncthreads();
    if (t < G) s->gtmS[t] = s->gtm[t] ? s->gtm[t] : 0xFFFFFFFFu;  // never ties
    __syncthreads();

    // ---- main loop: thread t = location t (t < 625) -------------------------
    if (t < NLOC) {
        const int loc = t;
        const float* xp = s->xc + (loc % 25) * 5;     // + g*128 + a
        const float* yp = s->yc + (loc / 25) * 5;     // + g*128 + a

        unsigned umax[A] = {0u, 0u, 0u, 0u, 0u};      // v>=0: bits monotone;
        int      arg [A] = {0, 0, 0, 0, 0};           // all-zero row -> arg 0
        int      keepm   = 0;

#pragma unroll 4
        for (int g = 0; g < G; g++) {
            const unsigned gm = s->gtmS[g];
#pragma unroll
            for (int a = 0; a < A; a++) {
                float inter = __fmul_rn(xp[g * 128 + a], yp[g * 128 + a]);
                float v = div6(inter, __fsub_rn(s->sag[g * 8 + a], inter));
                unsigned u = __float_as_uint(v);
                if (u > umax[a]) { umax[a] = u; arg[a] = g; }  // first-idx max
                if (u == gm) keepm |= 1 << a;
            }
        }

        const long movB = (long)Bn * NANCH * 6 + (long)bA * NANCH;
        const long btB  = (long)Bn * NANCH + (long)(bA * 4) * A * (S * S);
#pragma unroll
        for (int a = 0; a < A; a++) {
            const int n = loc * A + a;
            float maxv = __uint_as_float(umax[a]);
            int cls = -1;
            if (maxv >= THR_HIGH) cls = 1;
            if (maxv <= THR_LOW)  cls = 0;
            if (keepm & (1 << a)) cls = 1;
            g_cls[(long)bA * NPAD + n] = (signed char)cls;
            out[movB + n] = maxv;

            // bt deltas (argmax gt already in registers)
            float4 a4 = anchors[n];
            float4 q  = s->gtv[arg[a]];
            float aw = a4.z - a4.x + 1.0f, ah = a4.w - a4.y + 1.0f;
            float acx = a4.x + 0.5f * aw,  acy = a4.y + 0.5f * ah;
            float gw = q.z - q.x + 1.0f,   gh = q.w - q.y + 1.0f;
            float gcx = q.x + 0.5f * gw,   gcy = q.y + 0.5f * gh;
            long o = btB + (long)a * (S * S) + loc;
            out[o]             = __fdividef(gcx - acx, aw);
            out[o + NANCH]     = __fdividef(gcy - acy, ah);
            out[o + 2 * NANCH] = __logf(__fdividef(gw, aw));
            out[o + 3 * NANCH] = __logf(__fdividef(gh, ah));
        }
    }
    if (t < NPAD - NANCH)                              // pad tail -> -1
        g_cls[(long)bA * NPAD + NANCH + t] = -1;
}

// ---------------- K2: per-batch cumsum truncation, coalesced cls/bw ----------
__global__ void k_scan(float* __restrict__ out, int Bn) {
    __shared__ int wsum[32];
    __shared__ int s_pos;
    __shared__ signed char s_cls[NANCH + 3];
    const int bA = blockIdx.x, t = threadIdx.x;
    const int lane = t & 31, w = t >> 5;
    const int bL = Bn - 1;

    if (t == 0) s_pos = 0;
    __syncthreads();

    // pre-truncation pos count of LAST batch (post-trunc = min(raw, POS_NUM))
    const int NI = NPAD / 4;                             // 782 ints
    int lp = 0;
    if (t < NI) {
        int x = ((const int*)g_cls)[(long)bL * NI + t];
        lp = __popc(__vcmpeq4((unsigned)x, 0x01010101u)) >> 3;
    }
#pragma unroll
    for (int off = 16; off; off >>= 1) lp += __shfl_down_sync(0xffffffffu, lp, off);
    if (lane == 0 && lp) atomicAdd(&s_pos, lp);

    // own chunk of 4 (one aligned 32-bit load)
    int cloc[4];
    int pc = 0, nc = 0;
    if (t < NI) {
        int x = ((const int*)g_cls)[(long)bA * NI + t];
#pragma unroll
        for (int k = 0; k < 4; k++) {
            int c = (signed char)(x >> (8 * k));
            cloc[k] = c;
            pc += (c == 1);
            nc += (c == 0);
        }
    } else {
        cloc[0] = cloc[1] = cloc[2] = cloc[3] = -1;
    }

    // block-wide exclusive scan of packed (pos,neg) counts
    int v = (pc << 16) | nc;
    int inc = v;
#pragma unroll
    for (int off = 1; off < 32; off <<= 1) {
        int u = __shfl_up_sync(0xffffffffu, inc, off);
        if (lane >= off) inc += u;
    }
    if (lane == 31) wsum[w] = inc;
    __syncthreads();
    if (w == 0) {
        int x = wsum[lane];
        int xi = x;
#pragma unroll
        for (int off = 1; off < 32; off <<= 1) {
            int u = __shfl_up_sync(0xffffffffu, xi, off);
            if (lane >= off) xi += u;
        }
        wsum[lane] = xi - x;
    }
    __syncthreads();
    int exc = (inc - v) + wsum[w];
    int prun = exc >> 16;
    int nrun = exc & 0xffff;

    const int start = t * 4;
#pragma unroll
    for (int k = 0; k < 4; k++) {
        int n = start + k;
        if (n >= NANCH) break;
        int c = cloc[k];
        if (c == 1)      { prun++; if (prun > POS_NUM)   c = -1; }
        else if (c == 0) { nrun++; if (nrun > TOTAL_NUM) c = -1; }
        s_cls[n] = (signed char)c;
    }
    __syncthreads();

    const int pn = min(s_pos, POS_NUM);
    const float invp = 1.0f / (float)pn;                 // pn==0 -> inf (ref)
    const long clsB = (long)bA * NANCH;
    const long bwB  = (long)Bn * NANCH * 5 + clsB;

    for (int o = t; o < NANCH; o += 1024) {              // o = a*625+yx, coalesced
        int aa = o / (S * S), yx = o - aa * (S * S);
        int c = s_cls[yx * A + aa];                      // stride-5 LDS: no conflicts
        out[clsB + o] = (float)c;
        out[bwB + o]  = (c == 1) ? invp : 0.0f;
    }
}

// ---------------- launch ------------------------------------------------------
extern "C" void kernel_launch(void* const* d_in, const int* in_sizes, int n_in,
                              void* d_out, int out_size) {
    (void)n_in; (void)out_size;
    const float4* gt      = (const float4*)d_in[0];   // (B, G, 4)
    const float4* anchors = (const float4*)d_in[1];   // (N, 4)
    const int Bn = in_sizes[0] / (G * 4);             // 128
    float* out = (float*)d_out;

    static int smem_set = 0;
    if (!smem_set) {
        cudaFuncSetAttribute(k_iou, cudaFuncAttributeMaxDynamicSharedMemorySize,
                             (int)sizeof(SM));
        smem_set = 1;
    }
    k_iou <<<Bn, TPB, sizeof(SM)>>>(anchors, gt, out, Bn);
    k_scan<<<Bn, 1024>>>(out, Bn);
}